// round 3
// baseline (speedup 1.0000x reference)
#include <cuda_runtime.h>

#define BATCH 16
#define CIN   256
#define COUT  256
#define HGT   64
#define WID   64
#define SDIM  512
#define KW    3
#define EPSV  1e-8f

#define CICHUNK 8
#define NCHUNK  (CIN / CICHUNK)         // 32
#define COTILE  128
#define SW_CISTRIDE (9 * COTILE + 8)    // 1160 floats: pad 8 -> conflict-free STS/LDS
#define SX_ROWS 4
#define SX_COLS 68                      // 66 used (cols -1..64), pad to 68

// Scratch (allocation-free rule: __device__ globals)
__device__ float g_style[BATCH * CIN];
__device__ float g_denom[BATCH * COUT];

// ---------------------------------------------------------------------------
// Kernel 1: style[b,ci] = y[b,:] @ style_w[ci,:] + style_b[ci]
// ---------------------------------------------------------------------------
__global__ void style_kernel(const float* __restrict__ y,
                             const float* __restrict__ sw,
                             const float* __restrict__ sb) {
    int b = blockIdx.x;
    int ci = threadIdx.x;
    __shared__ float ys[SDIM];
    for (int s = ci; s < SDIM; s += blockDim.x) ys[s] = y[b * SDIM + s];
    __syncthreads();
    float acc = sb[ci];
    const float* wr = sw + (size_t)ci * SDIM;
#pragma unroll 8
    for (int s = 0; s < SDIM; s++) acc = fmaf(ys[s], wr[s], acc);
    g_style[b * CIN + ci] = acc;
}

// ---------------------------------------------------------------------------
// Kernel 2: denom[b,co] = 1/sqrt( sum_ci style[b,ci]^2 * sum_k w[co,ci,k]^2 + eps )
// ---------------------------------------------------------------------------
__global__ void denom_kernel(const float* __restrict__ w) {
    int co = blockIdx.x;
    int ci = threadIdx.x;
    const float* wp = w + (size_t)co * (CIN * 9) + ci * 9;
    float v = 0.f;
#pragma unroll
    for (int k = 0; k < 9; k++) v = fmaf(wp[k], wp[k], v);

    __shared__ float red[CIN];
    for (int b = 0; b < BATCH; b++) {
        float s = g_style[b * CIN + ci];
        red[ci] = s * s * v;
        __syncthreads();
        for (int off = 128; off > 0; off >>= 1) {
            if (ci < off) red[ci] += red[ci + off];
            __syncthreads();
        }
        if (ci == 0) g_denom[b * COUT + co] = 1.0f / sqrtf(red[0] + EPSV);
        __syncthreads();
    }
}

// ---------------------------------------------------------------------------
// Kernel 3: shared-weight conv with style folded into x, demod folded into output.
// Block: 128 cout x (2 rows x 64 cols) for one b. 256 threads, 8co x 8px each.
// Accumulation in packed fp32x2 (FFMA2) to reach 128 FMA/cyc/SM.
// ---------------------------------------------------------------------------
__global__ __launch_bounds__(256, 2)
void conv_kernel(const float* __restrict__ x,
                 const float* __restrict__ w,
                 const float* __restrict__ bias,
                 float* __restrict__ out) {
    __shared__ __align__(16) float sW[CICHUNK * SW_CISTRIDE];
    __shared__ __align__(16) float sX[CICHUNK * SX_ROWS * SX_COLS];
    __shared__ float sStyle[CIN];

    const int b   = blockIdx.z;
    const int co0 = blockIdx.y * COTILE;
    const int r0  = blockIdx.x * 2;
    const int tid = threadIdx.x;

    for (int i = tid; i < CIN; i += 256) sStyle[i] = g_style[b * CIN + i];

    const int cog     = tid >> 4;          // 0..15
    const int pxg     = tid & 15;          // 0..15
    const int orow    = pxg >> 3;          // 0..1
    const int colbase = (pxg & 7) * 8;     // 0..56
    const int cobase  = cog * 8;           // 0..120

    unsigned long long acc[8][4];
#pragma unroll
    for (int i = 0; i < 8; i++)
#pragma unroll
        for (int j = 0; j < 4; j++) acc[i][j] = 0ull;

    for (int chunk = 0; chunk < NCHUNK; chunk++) {
        const int ci0 = chunk * CICHUNK;
        __syncthreads();  // smem reusable (also orders sStyle fill on first iter)

        // --- load W chunk: [ci][tap][co], padded stride ---
#pragma unroll
        for (int it = 0; it < 4; it++) {
            int idx = tid + it * 256;      // 0..1023 = 128co x 8ci
            int co  = idx >> 3;
            int ci  = idx & 7;
            const float* gp = w + (size_t)(co0 + co) * (CIN * 9) + (ci0 + ci) * 9;
            float* sp = sW + ci * SW_CISTRIDE + co;
#pragma unroll
            for (int k = 0; k < 9; k++) sp[k * COTILE] = gp[k];
        }

        // --- load X halo tile, style-scaled, zero-padded ---
        for (int idx = tid; idx < CICHUNK * SX_ROWS * SX_COLS; idx += 256) {
            int ci  = idx / (SX_ROWS * SX_COLS);
            int rem = idx - ci * (SX_ROWS * SX_COLS);
            int rr  = rem / SX_COLS;
            int cc  = rem - rr * SX_COLS;
            int grow = r0 - 1 + rr;
            int gcol = cc - 1;
            float v = 0.f;
            if (grow >= 0 && grow < HGT && gcol >= 0 && gcol < WID && cc < 66) {
                v = x[(((size_t)(b * CIN + ci0 + ci)) * HGT + grow) * WID + gcol]
                    * sStyle[ci0 + ci];
            }
            sX[idx] = v;
        }
        __syncthreads();

        // --- compute: 8 ci x 9 taps x 8 co x 8 px ---
#pragma unroll
        for (int ci = 0; ci < CICHUNK; ci++) {
            const float* xrow = sX + ci * (SX_ROWS * SX_COLS) + orow * SX_COLS + colbase;
            const float* wrow = sW + ci * SW_CISTRIDE + cobase;
#pragma unroll
            for (int ky = 0; ky < 3; ky++) {
                float xv[10];
                const float* xr = xrow + ky * SX_COLS;
#pragma unroll
                for (int j = 0; j < 10; j++) xv[j] = xr[j];
#pragma unroll
                for (int kx = 0; kx < 3; kx++) {
                    unsigned long long xp[4];
#pragma unroll
                    for (int j = 0; j < 4; j++) {
                        asm("mov.b64 %0, {%1, %2};"
                            : "=l"(xp[j]) : "f"(xv[kx + 2 * j]), "f"(xv[kx + 2 * j + 1]));
                    }
                    const float* wp = wrow + (ky * 3 + kx) * COTILE;
#pragma unroll
                    for (int oc = 0; oc < 8; oc++) {
                        float wv = wp[oc];
                        unsigned long long wpk;
                        asm("mov.b64 %0, {%1, %1};" : "=l"(wpk) : "f"(wv));
#pragma unroll
                        for (int j = 0; j < 4; j++) {
                            asm("fma.rn.f32x2 %0, %1, %2, %0;"
                                : "+l"(acc[oc][j]) : "l"(wpk), "l"(xp[j]));
                        }
                    }
                }
            }
        }
    }

    // --- epilogue: demod scale + bias, vectorized stores ---
    const int gr = r0 + orow;
#pragma unroll
    for (int oc = 0; oc < 8; oc++) {
        int co = co0 + cobase + oc;
        float d  = g_denom[b * COUT + co];
        float bs = bias[co];
        float res[8];
#pragma unroll
        for (int j = 0; j < 4; j++) {
            float lo, hi;
            asm("mov.b64 {%0, %1}, %2;" : "=f"(lo), "=f"(hi) : "l"(acc[oc][j]));
            res[2 * j]     = fmaf(lo, d, bs);
            res[2 * j + 1] = fmaf(hi, d, bs);
        }
        float4* op = (float4*)(out + (((size_t)(b * COUT + co)) * HGT + gr) * WID + colbase);
        op[0] = make_float4(res[0], res[1], res[2], res[3]);
        op[1] = make_float4(res[4], res[5], res[6], res[7]);
    }
}

// ---------------------------------------------------------------------------
extern "C" void kernel_launch(void* const* d_in, const int* in_sizes, int n_in,
                              void* d_out, int out_size) {
    const float* x   = (const float*)d_in[0];  // [16,256,64,64]
    const float* y   = (const float*)d_in[1];  // [16,512]
    const float* w   = (const float*)d_in[2];  // [256,256,3,3]
    const float* bs  = (const float*)d_in[3];  // [256]
    const float* swt = (const float*)d_in[4];  // [256,512]
    const float* sbv = (const float*)d_in[5];  // [256]
    float* out = (float*)d_out;

    style_kernel<<<BATCH, CIN>>>(y, swt, sbv);
    denom_kernel<<<COUT, CIN>>>(w);

    dim3 grid(HGT / 2, COUT / COTILE, BATCH);  // (32, 2, 16)
    conv_kernel<<<grid, 256>>>(x, w, bs, out);
}

// round 4
// speedup vs baseline: 1.2601x; 1.2601x over previous
#include <cuda_runtime.h>

#define BATCH 16
#define CIN   256
#define COUT  256
#define HGT   64
#define WID   64
#define SDIM  512
#define EPSV  1e-8f

#define CICHUNK 8
#define NCHUNK  (CIN / CICHUNK)         // 32
#define COTILE  128
#define SW_CISTRIDE (9 * COTILE + 8)    // 1160 floats (even -> 8B aligned pairs)
#define SX_ROWS 4
#define SX_COLS 68                      // 66 used (cols -1..64), pad to 68

__device__ float g_style[BATCH * CIN];
__device__ float g_denom[BATCH * COUT];

// ---------------------------------------------------------------------------
// Kernel 1: style[b,ci] = y[b,:] @ style_w[ci,:] + style_b[ci]
// One warp per (b,ci). 512 blocks x 8 warps = 4096 warps.
// ---------------------------------------------------------------------------
__global__ void style_kernel(const float* __restrict__ y,
                             const float* __restrict__ sw,
                             const float* __restrict__ sb) {
    int widx = blockIdx.x * 8 + (threadIdx.x >> 5);   // 0..4095
    int lane = threadIdx.x & 31;
    int b  = widx >> 8;
    int ci = widx & 255;
    const float* yr = y + b * SDIM;
    const float* wr = sw + (size_t)ci * SDIM;
    float acc = 0.f;
#pragma unroll
    for (int s = lane; s < SDIM; s += 32) acc = fmaf(yr[s], wr[s], acc);
#pragma unroll
    for (int off = 16; off > 0; off >>= 1)
        acc += __shfl_xor_sync(0xffffffffu, acc, off);
    if (lane == 0) g_style[b * CIN + ci] = acc + sb[ci];
}

// ---------------------------------------------------------------------------
// Kernel 2: denom[b,co] = rsqrt( sum_ci style[b,ci]^2 * sum_k w[co,ci,k]^2 + eps )
// Block per co. Phase 1: v[ci] = sum_k w^2 (one sync). Phase 2: warp per 2 b.
// ---------------------------------------------------------------------------
__global__ void denom_kernel(const float* __restrict__ w) {
    int co = blockIdx.x;
    int ci = threadIdx.x;
    __shared__ float v[CIN];
    const float* wp = w + (size_t)co * (CIN * 9) + ci * 9;
    float s = 0.f;
#pragma unroll
    for (int k = 0; k < 9; k++) s = fmaf(wp[k], wp[k], s);
    v[ci] = s;
    __syncthreads();

    int warp = threadIdx.x >> 5;
    int lane = threadIdx.x & 31;
#pragma unroll
    for (int bb = 0; bb < 2; bb++) {
        int b = warp * 2 + bb;
        float acc = 0.f;
#pragma unroll
        for (int c = lane; c < CIN; c += 32) {
            float st = g_style[b * CIN + c];
            acc = fmaf(st * st, v[c], acc);
        }
#pragma unroll
        for (int off = 16; off > 0; off >>= 1)
            acc += __shfl_xor_sync(0xffffffffu, acc, off);
        if (lane == 0) g_denom[b * COUT + co] = rsqrtf(acc + EPSV);
    }
}

// ---------------------------------------------------------------------------
// Kernel 3: shared-weight conv, style folded into x, demod folded into output.
// Block: 128 cout x (2 rows x 64 cols) of one b. 256 threads: 8co x 8px each.
// Accumulators paired over oc (FFMA2); w pairs come straight from LDS.64.
// ---------------------------------------------------------------------------
__global__ __launch_bounds__(256, 2)
void conv_kernel(const float* __restrict__ x,
                 const float* __restrict__ w,
                 const float* __restrict__ bias,
                 float* __restrict__ out) {
    __shared__ __align__(16) float sW[CICHUNK * SW_CISTRIDE];
    __shared__ __align__(16) float sX[CICHUNK * SX_ROWS * SX_COLS];
    __shared__ float sStyle[CIN];

    const int b   = blockIdx.z;
    const int co0 = blockIdx.y * COTILE;
    const int r0  = blockIdx.x * 2;
    const int tid = threadIdx.x;

    for (int i = tid; i < CIN; i += 256) sStyle[i] = g_style[b * CIN + i];

    const int cog     = tid >> 4;          // 0..15
    const int pxg     = tid & 15;          // 0..15
    const int orow    = pxg >> 3;          // 0..1
    const int colbase = (pxg & 7) * 8;     // 0..56
    const int cobase  = cog * 8;           // 0..120

    // acc2[p][q]: p = pixel 0..7, q = oc-pair 0..3; .lo = oc 2q, .hi = oc 2q+1
    unsigned long long acc2[8][4];
#pragma unroll
    for (int p = 0; p < 8; p++)
#pragma unroll
        for (int q = 0; q < 4; q++) acc2[p][q] = 0ull;

    for (int chunk = 0; chunk < NCHUNK; chunk++) {
        const int ci0 = chunk * CICHUNK;
        __syncthreads();  // smem reuse (also orders sStyle fill on first iter)

        // --- load W chunk: [ci][tap][co] ---
#pragma unroll
        for (int it = 0; it < 4; it++) {
            int idx = tid + it * 256;      // 0..1023 = 128co x 8ci
            int co  = idx >> 3;
            int ci  = idx & 7;
            const float* gp = w + (size_t)(co0 + co) * (CIN * 9) + (ci0 + ci) * 9;
            float* sp = sW + ci * SW_CISTRIDE + co;
#pragma unroll
            for (int k = 0; k < 9; k++) sp[k * COTILE] = gp[k];
        }

        // --- load X halo tile, style-scaled, zero-padded ---
        for (int idx = tid; idx < CICHUNK * SX_ROWS * SX_COLS; idx += 256) {
            int ci  = idx / (SX_ROWS * SX_COLS);
            int rem = idx - ci * (SX_ROWS * SX_COLS);
            int rr  = rem / SX_COLS;
            int cc  = rem - rr * SX_COLS;
            int grow = r0 - 1 + rr;
            int gcol = cc - 1;
            float v = 0.f;
            if (grow >= 0 && grow < HGT && gcol >= 0 && gcol < WID && cc < 66) {
                v = x[(((size_t)(b * CIN + ci0 + ci)) * HGT + grow) * WID + gcol]
                    * sStyle[ci0 + ci];
            }
            sX[idx] = v;
        }
        __syncthreads();

        // --- compute: 8 ci x 3 ky x 3 kx x 8 px x 4 oc-pairs ---
#pragma unroll
        for (int ci = 0; ci < CICHUNK; ci++) {
            const float* xrow = sX + ci * (SX_ROWS * SX_COLS) + orow * SX_COLS + colbase;
            const float* wrow = sW + ci * SW_CISTRIDE + cobase;
#pragma unroll
            for (int ky = 0; ky < 3; ky++) {
                // vectorized x loads: 16B-aligned (all index terms mult of 4)
                float xv[10];
                const float* xr = xrow + ky * SX_COLS;
                {
                    float4 a = *(const float4*)(xr);
                    float4 c = *(const float4*)(xr + 4);
                    float2 e = *(const float2*)(xr + 8);
                    xv[0]=a.x; xv[1]=a.y; xv[2]=a.z; xv[3]=a.w;
                    xv[4]=c.x; xv[5]=c.y; xv[6]=c.z; xv[7]=c.w;
                    xv[8]=e.x; xv[9]=e.y;
                }
#pragma unroll
                for (int kx = 0; kx < 3; kx++) {
                    // w pairs: direct 64-bit LDS, no packing movs
                    const float* wp = wrow + (ky * 3 + kx) * COTILE;
                    unsigned long long wq[4];
#pragma unroll
                    for (int q = 0; q < 4; q++)
                        wq[q] = *(const unsigned long long*)(wp + 2 * q);
#pragma unroll
                    for (int p = 0; p < 8; p++) {
                        unsigned long long xb;
                        asm("mov.b64 %0, {%1, %1};" : "=l"(xb) : "f"(xv[kx + p]));
#pragma unroll
                        for (int q = 0; q < 4; q++) {
                            asm("fma.rn.f32x2 %0, %1, %2, %0;"
                                : "+l"(acc2[p][q]) : "l"(wq[q]), "l"(xb));
                        }
                    }
                }
            }
        }
    }

    // --- epilogue: demod scale + bias, vectorized stores ---
    const int gr = r0 + orow;
#pragma unroll
    for (int q = 0; q < 4; q++) {
        int oc0 = co0 + cobase + 2 * q;
        float d0 = g_denom[b * COUT + oc0];
        float d1 = g_denom[b * COUT + oc0 + 1];
        float b0 = bias[oc0];
        float b1 = bias[oc0 + 1];
        float r0v[8], r1v[8];
#pragma unroll
        for (int p = 0; p < 8; p++) {
            float lo, hi;
            asm("mov.b64 {%0, %1}, %2;" : "=f"(lo), "=f"(hi) : "l"(acc2[p][q]));
            r0v[p] = fmaf(lo, d0, b0);
            r1v[p] = fmaf(hi, d1, b1);
        }
        float4* op0 = (float4*)(out + (((size_t)(b * COUT + oc0)) * HGT + gr) * WID + colbase);
        float4* op1 = (float4*)(out + (((size_t)(b * COUT + oc0 + 1)) * HGT + gr) * WID + colbase);
        op0[0] = make_float4(r0v[0], r0v[1], r0v[2], r0v[3]);
        op0[1] = make_float4(r0v[4], r0v[5], r0v[6], r0v[7]);
        op1[0] = make_float4(r1v[0], r1v[1], r1v[2], r1v[3]);
        op1[1] = make_float4(r1v[4], r1v[5], r1v[6], r1v[7]);
    }
}

// ---------------------------------------------------------------------------
extern "C" void kernel_launch(void* const* d_in, const int* in_sizes, int n_in,
                              void* d_out, int out_size) {
    const float* x   = (const float*)d_in[0];  // [16,256,64,64]
    const float* y   = (const float*)d_in[1];  // [16,512]
    const float* w   = (const float*)d_in[2];  // [256,256,3,3]
    const float* bs  = (const float*)d_in[3];  // [256]
    const float* swt = (const float*)d_in[4];  // [256,512]
    const float* sbv = (const float*)d_in[5];  // [256]
    float* out = (float*)d_out;

    style_kernel<<<BATCH * CIN / 8, 256>>>(y, swt, sbv);
    denom_kernel<<<COUT, 256>>>(w);

    dim3 grid(HGT / 2, COUT / COTILE, BATCH);  // (32, 2, 16)
    conv_kernel<<<grid, 256>>>(x, w, bs, out);
}